// round 5
// baseline (speedup 1.0000x reference)
#include <cuda_runtime.h>
#include <math.h>

#define NE   16
#define NU   8
#define NA   4
#define NSV  256
#define NPV  32
#define NFB  4
#define NDET 16
#define SVOUT 832   // 3*NSV + 2*NPV
#define S0IN  56    // 3*(4*NA) + 2*4

__global__ __launch_bounds__(256, 2)
void ansatz_kernel(const float* __restrict__ r,   const float* __restrict__ a,
                   const float* __restrict__ sW0, const float* __restrict__ sb0,
                   const float* __restrict__ sW,  const float* __restrict__ sb,
                   const float* __restrict__ pW0, const float* __restrict__ pb0,
                   const float* __restrict__ pW,  const float* __restrict__ pb,
                   const float* __restrict__ vW,  const float* __restrict__ vb,
                   const float* __restrict__ wuW, const float* __restrict__ wub,
                   const float* __restrict__ wdW, const float* __restrict__ wdb,
                   const float* __restrict__ wfW, float* __restrict__ out)
{
    __shared__ __align__(16) float s_sv[NE][NSV];      // 16 KB
    __shared__ __align__(16) float s_blk0[NE][S0IN];   // 3.5 KB
    __shared__ float s_mu[NSV], s_md[NSV];
    __shared__ __align__(16) float s_pu[NE][NPV], s_pd[NE][NPV];
    __shared__ __align__(16) float s_pw[NPV*NPV];      // 4 KB (also holds pW0 4x32)
    __shared__ float s_pb[NPV];
    __shared__ float s_r[NE][3];
    __shared__ float s_a[NA][3];
    __shared__ float s_env[NE];
    __shared__ float s_sw[2][8][128];                  // 8 KB
    __shared__ float s_dsign[32], s_dld[32];

    const int tid = threadIdx.x;
    const int b   = blockIdx.x;

    // ---- load geometry ----
    if (tid < NE*3) ((float*)s_r)[tid] = r[b*NE*3 + tid];
    if (tid < NA*3) ((float*)s_a)[tid] = a[tid];
    __syncthreads();

    // ---- ra features -> blk0 cols [0,16) ----
    if (tid < NE*NA) {
        int e = tid >> 2, at = tid & 3;
        float dx = s_r[e][0]-s_a[at][0];
        float dy = s_r[e][1]-s_a[at][1];
        float dz = s_r[e][2]-s_a[at][2];
        float len = sqrtf(dx*dx+dy*dy+dz*dz);
        s_blk0[e][at*4+0]=dx; s_blk0[e][at*4+1]=dy;
        s_blk0[e][at*4+2]=dz; s_blk0[e][at*4+3]=len;
    }
    // ---- p0: thread owns pair (pi, pj); rr[i,j] = r[j]-r[i]; diag +1 only in the norm ----
    const int pi = tid >> 4;
    const int pj = tid & 15;
    float p0[4];
    {
        float dx = s_r[pj][0]-s_r[pi][0];
        float dy = s_r[pj][1]-s_r[pi][1];
        float dz = s_r[pj][2]-s_r[pi][2];
        float ax=dx, ay=dy, az=dz;
        if (pi==pj) { ax+=1.f; ay+=1.f; az+=1.f; }
        p0[0]=dx; p0[1]=dy; p0[2]=dz; p0[3]=sqrtf(ax*ax+ay*ay+az*az);
    }
    // zero pu/pd cols 0..3 for layer-0 reduction
    if (tid < 64) { int e=tid>>2,c=tid&3; s_pu[e][c]=0.f; s_pd[e][c]=0.f; }
    __syncthreads();

    // ---- envelope ----
    if (tid < NE) {
        float s=0.f;
        #pragma unroll
        for (int at=0; at<NA; ++at) s += expf(-s_blk0[tid][at*4+3]);
        s_env[tid]=s;
    }
    // ---- mu0/md0 -> blk0 cols [16,48) ----
    if (tid < 16) {
        float mu=0.f, md=0.f;
        for (int e=0;e<8;e++)  mu += s_blk0[e][tid];
        for (int e=8;e<16;e++) md += s_blk0[e][tid];
        mu *= 0.125f; md *= 0.125f;
        for (int e=0;e<NE;e++){ s_blk0[e][16+tid]=mu; s_blk0[e][32+tid]=md; }
    }
    // ---- pu0/pd0 via smem atomics ----
    {
        float* dst = (pi<NU) ? &s_pu[pj][0] : &s_pd[pj][0];
        #pragma unroll
        for (int c=0;c<4;c++) atomicAdd(&dst[c], p0[c]*0.125f);
    }
    // stage pW0 (4x32), pb0
    if (tid < 128) s_pw[tid] = pW0[tid];
    if (tid < NPV) s_pb[tid] = pb0[tid];
    __syncthreads();
    // blk0 cols [48,56)
    if (tid < 64) {
        int e=tid>>2, c=tid&3;
        s_blk0[e][48+c]=s_pu[e][c];
        s_blk0[e][52+c]=s_pd[e][c];
    }
    __syncthreads();

    // ---- layer 0: s_v = tanh(blk0 @ sW0 + sb0) ----
    float acc[NE];
    {
        const int j = tid;
        float bb = __ldg(&sb0[j]);
        #pragma unroll
        for (int e=0;e<NE;e++) acc[e]=bb;
        for (int k=0;k<S0IN;k++) {
            float w = __ldg(&sW0[k*NSV+j]);
            #pragma unroll
            for (int e=0;e<NE;e++) acc[e] += s_blk0[e][k]*w;
        }
    }
    // ---- layer 0 p: pv = tanh(p0 @ pW0 + pb0) ----
    float pv[NPV];
    {
        #pragma unroll
        for (int c=0;c<NPV;c++) pv[c]=s_pb[c];
        #pragma unroll
        for (int k=0;k<4;k++) {
            float aa = p0[k];
            #pragma unroll
            for (int c=0;c<NPV;c++) pv[c] += aa*s_pw[k*NPV+c];
        }
        #pragma unroll
        for (int c=0;c<NPV;c++) pv[c]=tanhf(pv[c]);
    }
    #pragma unroll
    for (int e=0;e<NE;e++) s_sv[e][tid]=tanhf(acc[e]);
    __syncthreads();

    // ---- 4 residual layers + final vW layer ----
    for (int l=0; l<NFB+1; ++l) {
        // fb_block quantities from current s_v / p_v
        {
            float mu=0.f, md=0.f;
            #pragma unroll
            for (int e=0;e<8;e++)  mu += s_sv[e][tid];
            #pragma unroll
            for (int e=8;e<16;e++) md += s_sv[e][tid];
            s_mu[tid]=mu*0.125f; s_md[tid]=md*0.125f;
        }
        ((float*)s_pu)[tid] = 0.f; ((float*)s_pu)[tid+256] = 0.f;
        ((float*)s_pd)[tid] = 0.f; ((float*)s_pd)[tid+256] = 0.f;
        __syncthreads();
        {
            float* dst = (pi<NU)? &s_pu[pj][0] : &s_pd[pj][0];
            #pragma unroll
            for (int c=0;c<NPV;c++) atomicAdd(&dst[c], pv[c]*0.125f);
        }
        if (l<NFB) {
            #pragma unroll
            for (int q=0;q<4;q++) s_pw[tid+q*256] = pW[l*NPV*NPV + tid + q*256];
            if (tid<NPV) s_pb[tid]=pb[l*NPV+tid];
        }
        __syncthreads();

        const float* W    = (l<NFB)? (sW + (size_t)l*SVOUT*NSV) : vW;
        const float* bias = (l<NFB)? (sb + l*NSV) : vb;
        const int j = tid;
        // shared (mu/md) contribution: identical for all 16 rows
        float gg = __ldg(&bias[j]);
        for (int k=0;k<NSV;k++) gg += s_mu[k]*__ldg(&W[(NSV+k)*NSV + j]);
        for (int k=0;k<NSV;k++) gg += s_md[k]*__ldg(&W[(2*NSV+k)*NSV + j]);
        #pragma unroll
        for (int e=0;e<NE;e++) acc[e]=gg;
        // pu/pd contribution
        for (int k=0;k<NPV;k++) {
            float w1=__ldg(&W[(3*NSV+k)*NSV + j]);
            float w2=__ldg(&W[(3*NSV+NPV+k)*NSV + j]);
            #pragma unroll
            for (int e=0;e<NE;e++) acc[e] += s_pu[e][k]*w1 + s_pd[e][k]*w2;
        }
        // main s_v contribution
        for (int k=0;k<NSV;k+=4) {
            float w0=__ldg(&W[(k+0)*NSV + j]);
            float w1=__ldg(&W[(k+1)*NSV + j]);
            float w2=__ldg(&W[(k+2)*NSV + j]);
            float w3=__ldg(&W[(k+3)*NSV + j]);
            #pragma unroll
            for (int e=0;e<NE;e++) {
                float4 s4 = *(const float4*)&s_sv[e][k];
                acc[e] = fmaf(s4.x,w0,fmaf(s4.y,w1,fmaf(s4.z,w2,fmaf(s4.w,w3,acc[e]))));
            }
        }
        #pragma unroll
        for (int e=0;e<NE;e++) {
            float t = tanhf(acc[e]);
            acc[e] = (l<NFB)? (t + s_sv[e][j]) : t;
        }
        __syncthreads();           // all reads of old s_v done
        #pragma unroll
        for (int e=0;e<NE;e++) s_sv[e][j]=acc[e];
        // p update (registers only)
        if (l<NFB) {
            float pn[NPV];
            #pragma unroll
            for (int c=0;c<NPV;c++) pn[c]=s_pb[c];
            #pragma unroll
            for (int k=0;k<NPV;k++) {
                float aa=pv[k];
                #pragma unroll
                for (int c=0;c<NPV;c+=4) {
                    float4 w4 = *(const float4*)&s_pw[k*NPV+c];
                    pn[c]+=aa*w4.x; pn[c+1]+=aa*w4.y; pn[c+2]+=aa*w4.z; pn[c+3]+=aa*w4.w;
                }
            }
            #pragma unroll
            for (int c=0;c<NPV;c++) pv[c]=tanhf(pn[c])+pv[c];
        }
        __syncthreads();
    }

    // ---- orbitals: sw = s_v[spin] @ W + b ----
    {
        const int m    = tid & 127;
        const int half = tid >> 7;
        #pragma unroll
        for (int spin=0; spin<2; ++spin) {
            const float* Wo = spin? wdW : wuW;
            const float* bo = spin? wdb : wub;
            const int eb = spin*8 + half*4;
            float bm = __ldg(&bo[m]);
            float o0=bm,o1=bm,o2=bm,o3=bm;
            for (int k=0;k<NSV;k++) {
                float w = __ldg(&Wo[k*128+m]);
                o0 += s_sv[eb+0][k]*w;
                o1 += s_sv[eb+1][k]*w;
                o2 += s_sv[eb+2][k]*w;
                o3 += s_sv[eb+3][k]*w;
            }
            s_sw[spin][half*4+0][m]=o0;
            s_sw[spin][half*4+1][m]=o1;
            s_sw[spin][half*4+2][m]=o2;
            s_sw[spin][half*4+3][m]=o3;
        }
    }
    __syncthreads();

    // ---- 32 slogdets of 8x8 (one per thread) ----
    if (tid < 32) {
        const int spin = tid>>4, d = tid&15;
        float M[8][8];
        for (int jr=0;jr<8;jr++)
            for (int ic=0;ic<8;ic++)
                M[jr][ic] = s_sw[spin][ic][jr*NDET+d] * s_env[spin*8+ic];
        float sign=1.f, ld=0.f;
        for (int k=0;k<8;k++) {
            int p=k; float mv=fabsf(M[k][k]);
            for (int rr2=k+1; rr2<8; rr2++) { float v=fabsf(M[rr2][k]); if (v>mv){mv=v;p=rr2;} }
            if (p!=k) { for (int c=0;c<8;c++){float t=M[k][c];M[k][c]=M[p][c];M[p][c]=t;} sign=-sign; }
            float piv = M[k][k];
            if (piv<0.f) sign=-sign;
            ld += logf(fabsf(piv));
            float inv = 1.f/piv;
            for (int rr2=k+1; rr2<8; rr2++) {
                float f = M[rr2][k]*inv;
                for (int c=k+1;c<8;c++) M[rr2][c] -= f*M[k][c];
            }
        }
        s_dsign[tid]=sign; s_dld[tid]=ld;
    }
    __syncthreads();

    // ---- combine determinants ----
    if (tid==0) {
        float mmax=-INFINITY;
        float ldt[NDET], sg[NDET];
        #pragma unroll
        for (int d=0;d<NDET;d++) {
            ldt[d]=s_dld[d]+s_dld[16+d];
            sg[d] =s_dsign[d]*s_dsign[16+d];
            mmax = fmaxf(mmax, ldt[d]);
        }
        float psi=0.f;
        #pragma unroll
        for (int d=0;d<NDET;d++) psi += sg[d]*expf(ldt[d]-mmax)*__ldg(&wfW[d]);
        out[b] = logf(fabsf(psi)) + mmax;
    }
}

extern "C" void kernel_launch(void* const* d_in, const int* in_sizes, int n_in,
                              void* d_out, int out_size) {
    const float* r   = (const float*)d_in[0];
    const float* a   = (const float*)d_in[1];
    const float* sW0 = (const float*)d_in[2];
    const float* sb0 = (const float*)d_in[3];
    const float* sW  = (const float*)d_in[4];
    const float* sb  = (const float*)d_in[5];
    const float* pW0 = (const float*)d_in[6];
    const float* pb0 = (const float*)d_in[7];
    const float* pW  = (const float*)d_in[8];
    const float* pb  = (const float*)d_in[9];
    const float* vW  = (const float*)d_in[10];
    const float* vb  = (const float*)d_in[11];
    const float* wuW = (const float*)d_in[12];
    const float* wub = (const float*)d_in[13];
    const float* wdW = (const float*)d_in[14];
    const float* wdb = (const float*)d_in[15];
    const float* wfW = (const float*)d_in[16];
    float* out = (float*)d_out;

    int B = in_sizes[0] / (NE*3);
    ansatz_kernel<<<B, 256>>>(r,a,sW0,sb0,sW,sb,pW0,pb0,pW,pb,vW,vb,
                              wuW,wub,wdW,wdb,wfW,out);
}

// round 9
// speedup vs baseline: 1.0880x; 1.0880x over previous
#include <cuda_runtime.h>
#include <math.h>

#define NE   16
#define NU   8
#define NA   4
#define NSV  256
#define NPV  32
#define NFB  4
#define NDET 16
#define SVOUT 832   // 3*NSV + 2*NPV
#define S0IN  56    // 3*(4*NA) + 2*4
#define NLAY 5      // 4 residual layers + final vW layer

__global__ __launch_bounds__(256, 3)
void ansatz_kernel(const float* __restrict__ r,   const float* __restrict__ a,
                   const float* __restrict__ sW0, const float* __restrict__ sb0,
                   const float* __restrict__ sW,  const float* __restrict__ sb,
                   const float* __restrict__ pW0, const float* __restrict__ pb0,
                   const float* __restrict__ pW,  const float* __restrict__ pb,
                   const float* __restrict__ vW,  const float* __restrict__ vb,
                   const float* __restrict__ wuW, const float* __restrict__ wub,
                   const float* __restrict__ wdW, const float* __restrict__ wdb,
                   const float* __restrict__ wfW, float* __restrict__ out)
{
    __shared__ __align__(16) float s_sv[NE][NSV];            // 16 KB
    __shared__ __align__(16) float s_blk0[NE][S0IN];         // 3.5 KB
    __shared__ __align__(16) float s_mu[NSV], s_md[NSV];     // 2 KB
    __shared__ __align__(16) float s_puL[NLAY][NE][NPV];     // 10 KB (p-mean snapshots, up-spin)
    __shared__ __align__(16) float s_pdL[NLAY][NE][NPV];     // 10 KB (down-spin)
    __shared__ __align__(16) float s_pw[NPV*NPV];            // 4 KB (pW0 then pW[i])
    __shared__ float s_pb[NPV];
    __shared__ float s_pu0[NE][4], s_pd0[NE][4];
    __shared__ float s_r[NE][3];
    __shared__ float s_a[NA][3];
    __shared__ float s_env[NE];
    __shared__ float s_dsign[32], s_dld[32];
    // orbital buffer (2*8*128 floats = 8KB) aliased over snapshots 0..3 of s_puL,
    // which are dead by the time orbitals are computed (final layer reads only [4]).
    float (*s_sw)[8][128] = reinterpret_cast<float(*)[8][128]>(&s_puL[0][0][0]);

    const int tid = threadIdx.x;
    const int b   = blockIdx.x;

    // ---- load geometry ----
    if (tid < NE*3) ((float*)s_r)[tid] = r[b*NE*3 + tid];
    if (tid < NA*3) ((float*)s_a)[tid] = a[tid];
    // zero all mean snapshots (and s_pu0/s_pd0 zone separately below)
    for (int i = tid; i < NLAY*NE*NPV; i += 256) {
        ((float*)s_puL)[i] = 0.f;
        ((float*)s_pdL)[i] = 0.f;
    }
    if (tid < 64) { int e=tid>>2, c=tid&3; s_pu0[e][c]=0.f; s_pd0[e][c]=0.f; }
    __syncthreads();

    // ---- ra features -> blk0 cols [0,16) ----
    if (tid < NE*NA) {
        int e = tid >> 2, at = tid & 3;
        float dx = s_r[e][0]-s_a[at][0];
        float dy = s_r[e][1]-s_a[at][1];
        float dz = s_r[e][2]-s_a[at][2];
        float len = sqrtf(dx*dx+dy*dy+dz*dz);
        s_blk0[e][at*4+0]=dx; s_blk0[e][at*4+1]=dy;
        s_blk0[e][at*4+2]=dz; s_blk0[e][at*4+3]=len;
    }
    // ---- p0: thread owns pair (pi, pj); rr[i,j] = r[j]-r[i]; diag +1 only inside the norm ----
    const int pi = tid >> 4;
    const int pj = tid & 15;
    float p0[4];
    {
        float dx = s_r[pj][0]-s_r[pi][0];
        float dy = s_r[pj][1]-s_r[pi][1];
        float dz = s_r[pj][2]-s_r[pi][2];
        float ax=dx, ay=dy, az=dz;
        if (pi==pj) { ax+=1.f; ay+=1.f; az+=1.f; }
        p0[0]=dx; p0[1]=dy; p0[2]=dz; p0[3]=sqrtf(ax*ax+ay*ay+az*az);
    }
    __syncthreads();

    // ---- envelope ----
    if (tid < NE) {
        float s=0.f;
        #pragma unroll
        for (int at=0; at<NA; ++at) s += expf(-s_blk0[tid][at*4+3]);
        s_env[tid]=s;
    }
    // ---- mu0/md0 -> blk0 cols [16,48) ----
    if (tid < 16) {
        float mu=0.f, md=0.f;
        for (int e=0;e<8;e++)  mu += s_blk0[e][tid];
        for (int e=8;e<16;e++) md += s_blk0[e][tid];
        mu *= 0.125f; md *= 0.125f;
        for (int e=0;e<NE;e++){ s_blk0[e][16+tid]=mu; s_blk0[e][32+tid]=md; }
    }
    // ---- raw p means via smem atomics ----
    {
        float* dst = (pi<NU) ? &s_pu0[pj][0] : &s_pd0[pj][0];
        #pragma unroll
        for (int c=0;c<4;c++) atomicAdd(&dst[c], p0[c]*0.125f);
    }
    // stage pW0 (4x32), pb0
    if (tid < 128) s_pw[tid] = pW0[tid];
    if (tid < NPV) s_pb[tid] = pb0[tid];
    __syncthreads();
    // blk0 cols [48,56)
    if (tid < 64) {
        int e=tid>>2, c=tid&3;
        s_blk0[e][48+c]=s_pu0[e][c];
        s_blk0[e][52+c]=s_pd0[e][c];
    }
    __syncthreads();

    // ---- p layer 0: pv = tanh(p0 @ pW0 + pb0) ----
    float pv[NPV];
    {
        #pragma unroll
        for (int c=0;c<NPV;c++) pv[c]=s_pb[c];
        #pragma unroll
        for (int k=0;k<4;k++) {
            float aa = p0[k];
            #pragma unroll
            for (int c=0;c<NPV;c++) pv[c] += aa*s_pw[k*NPV+c];
        }
        #pragma unroll
        for (int c=0;c<NPV;c++) pv[c]=tanhf(pv[c]);
    }

    // ---- s layer 0: s_v = tanh(blk0 @ sW0 + sb0) ----
    float acc[NE];
    {
        const int j = tid;
        float bb = __ldg(&sb0[j]);
        #pragma unroll
        for (int e=0;e<NE;e++) acc[e]=bb;
        for (int k=0;k<S0IN;k++) {
            float w = __ldg(&sW0[k*NSV+j]);
            #pragma unroll
            for (int e=0;e<NE;e++) acc[e] += s_blk0[e][k]*w;
        }
        #pragma unroll
        for (int e=0;e<NE;e++) s_sv[e][tid]=tanhf(acc[e]);
    }

    // ================= p-stream phase: run all p layers, record mean snapshots =================
    for (int i=0; i<NLAY; ++i) {
        {
            float* dst = (pi<NU)? &s_puL[i][pj][0] : &s_pdL[i][pj][0];
            #pragma unroll
            for (int c=0;c<NPV;c++) atomicAdd(&dst[c], pv[c]*0.125f);
        }
        if (i<NFB) {
            __syncthreads();    // prior s_pw consumers done
            #pragma unroll
            for (int q=0;q<4;q++) s_pw[tid+q*256] = pW[i*NPV*NPV + tid + q*256];
            if (tid<NPV) s_pb[tid]=pb[i*NPV+tid];
            __syncthreads();
            float pn[NPV];
            #pragma unroll
            for (int c=0;c<NPV;c++) pn[c]=s_pb[c];
            #pragma unroll
            for (int k=0;k<NPV;k++) {
                float aa=pv[k];
                #pragma unroll
                for (int c=0;c<NPV;c+=4) {
                    float4 w4 = *(const float4*)&s_pw[k*NPV+c];
                    pn[c]+=aa*w4.x; pn[c+1]+=aa*w4.y; pn[c+2]+=aa*w4.z; pn[c+3]+=aa*w4.w;
                }
            }
            #pragma unroll
            for (int c=0;c<NPV;c++) pv[c]=tanhf(pn[c])+pv[c];
        }
    }
    __syncthreads();   // snapshots + s_sv visible for the s-phase

    // ================= s-stream phase: 4 residual layers + final vW layer =================
    for (int l=0; l<NLAY; ++l) {
        {
            float mu=0.f, md=0.f;
            #pragma unroll
            for (int e=0;e<8;e++)  mu += s_sv[e][tid];
            #pragma unroll
            for (int e=8;e<16;e++) md += s_sv[e][tid];
            s_mu[tid]=mu*0.125f; s_md[tid]=md*0.125f;
        }
        __syncthreads();   // mu/md and s_sv stable for reads

        const float* W    = (l<NFB)? (sW + (size_t)l*SVOUT*NSV) : vW;
        const float* bias = (l<NFB)? (sb + l*NSV) : vb;
        const int j = tid;

        // shared (mu/md) contribution: identical for all 16 rows
        float gg = __ldg(&bias[j]);
        for (int k=0;k<NSV;k+=4) {
            float4 m4 = *(const float4*)&s_mu[k];
            float w0=__ldg(&W[(NSV+k+0)*NSV + j]);
            float w1=__ldg(&W[(NSV+k+1)*NSV + j]);
            float w2=__ldg(&W[(NSV+k+2)*NSV + j]);
            float w3=__ldg(&W[(NSV+k+3)*NSV + j]);
            gg = fmaf(m4.x,w0,fmaf(m4.y,w1,fmaf(m4.z,w2,fmaf(m4.w,w3,gg))));
        }
        for (int k=0;k<NSV;k+=4) {
            float4 m4 = *(const float4*)&s_md[k];
            float w0=__ldg(&W[(2*NSV+k+0)*NSV + j]);
            float w1=__ldg(&W[(2*NSV+k+1)*NSV + j]);
            float w2=__ldg(&W[(2*NSV+k+2)*NSV + j]);
            float w3=__ldg(&W[(2*NSV+k+3)*NSV + j]);
            gg = fmaf(m4.x,w0,fmaf(m4.y,w1,fmaf(m4.z,w2,fmaf(m4.w,w3,gg))));
        }
        #pragma unroll
        for (int e=0;e<NE;e++) acc[e]=gg;

        // pu/pd contribution from snapshot l (float4 over k)
        for (int kb=0;kb<NPV;kb+=4) {
            float u0=__ldg(&W[(3*NSV+kb+0)*NSV + j]);
            float u1=__ldg(&W[(3*NSV+kb+1)*NSV + j]);
            float u2=__ldg(&W[(3*NSV+kb+2)*NSV + j]);
            float u3=__ldg(&W[(3*NSV+kb+3)*NSV + j]);
            float d0=__ldg(&W[(3*NSV+NPV+kb+0)*NSV + j]);
            float d1=__ldg(&W[(3*NSV+NPV+kb+1)*NSV + j]);
            float d2=__ldg(&W[(3*NSV+NPV+kb+2)*NSV + j]);
            float d3=__ldg(&W[(3*NSV+NPV+kb+3)*NSV + j]);
            #pragma unroll
            for (int e=0;e<NE;e++) {
                float4 u4 = *(const float4*)&s_puL[l][e][kb];
                float4 d4 = *(const float4*)&s_pdL[l][e][kb];
                float t = acc[e];
                t = fmaf(u4.x,u0,fmaf(u4.y,u1,fmaf(u4.z,u2,fmaf(u4.w,u3,t))));
                t = fmaf(d4.x,d0,fmaf(d4.y,d1,fmaf(d4.z,d2,fmaf(d4.w,d3,t))));
                acc[e]=t;
            }
        }

        // main s_v contribution
        for (int k=0;k<NSV;k+=4) {
            float w0=__ldg(&W[(k+0)*NSV + j]);
            float w1=__ldg(&W[(k+1)*NSV + j]);
            float w2=__ldg(&W[(k+2)*NSV + j]);
            float w3=__ldg(&W[(k+3)*NSV + j]);
            #pragma unroll
            for (int e=0;e<NE;e++) {
                float4 s4 = *(const float4*)&s_sv[e][k];
                acc[e] = fmaf(s4.x,w0,fmaf(s4.y,w1,fmaf(s4.z,w2,fmaf(s4.w,w3,acc[e]))));
            }
        }
        #pragma unroll
        for (int e=0;e<NE;e++) {
            float t = tanhf(acc[e]);
            acc[e] = (l<NFB)? (t + s_sv[e][j]) : t;
        }
        __syncthreads();           // all reads of old s_v done
        #pragma unroll
        for (int e=0;e<NE;e++) s_sv[e][j]=acc[e];
    }
    __syncthreads();   // final s_sv visible; snapshots 0..3 now dead -> s_sw may alias

    // ---- orbitals: sw = s_v[spin] @ W + b (float4 over k) ----
    {
        const int m    = tid & 127;
        const int half = tid >> 7;
        #pragma unroll
        for (int spin=0; spin<2; ++spin) {
            const float* Wo = spin? wdW : wuW;
            const float* bo = spin? wdb : wub;
            const int eb = spin*8 + half*4;
            float bm = __ldg(&bo[m]);
            float o0=bm,o1=bm,o2=bm,o3=bm;
            for (int k=0;k<NSV;k+=4) {
                float w0=__ldg(&Wo[(k+0)*128+m]);
                float w1=__ldg(&Wo[(k+1)*128+m]);
                float w2=__ldg(&Wo[(k+2)*128+m]);
                float w3=__ldg(&Wo[(k+3)*128+m]);
                float4 a0=*(const float4*)&s_sv[eb+0][k];
                float4 a1=*(const float4*)&s_sv[eb+1][k];
                float4 a2=*(const float4*)&s_sv[eb+2][k];
                float4 a3=*(const float4*)&s_sv[eb+3][k];
                o0 = fmaf(a0.x,w0,fmaf(a0.y,w1,fmaf(a0.z,w2,fmaf(a0.w,w3,o0))));
                o1 = fmaf(a1.x,w0,fmaf(a1.y,w1,fmaf(a1.z,w2,fmaf(a1.w,w3,o1))));
                o2 = fmaf(a2.x,w0,fmaf(a2.y,w1,fmaf(a2.z,w2,fmaf(a2.w,w3,o2))));
                o3 = fmaf(a3.x,w0,fmaf(a3.y,w1,fmaf(a3.z,w2,fmaf(a3.w,w3,o3))));
            }
            s_sw[spin][half*4+0][m]=o0;
            s_sw[spin][half*4+1][m]=o1;
            s_sw[spin][half*4+2][m]=o2;
            s_sw[spin][half*4+3][m]=o3;
        }
    }
    __syncthreads();

    // ---- 32 slogdets of 8x8 (one per thread) ----
    if (tid < 32) {
        const int spin = tid>>4, d = tid&15;
        float M[8][8];
        for (int jr=0;jr<8;jr++)
            for (int ic=0;ic<8;ic++)
                M[jr][ic] = s_sw[spin][ic][jr*NDET+d] * s_env[spin*8+ic];
        float sign=1.f, ld=0.f;
        for (int k=0;k<8;k++) {
            int p=k; float mv=fabsf(M[k][k]);
            for (int rr2=k+1; rr2<8; rr2++) { float v=fabsf(M[rr2][k]); if (v>mv){mv=v;p=rr2;} }
            if (p!=k) { for (int c=0;c<8;c++){float t=M[k][c];M[k][c]=M[p][c];M[p][c]=t;} sign=-sign; }
            float piv = M[k][k];
            if (piv<0.f) sign=-sign;
            ld += logf(fabsf(piv));
            float inv = 1.f/piv;
            for (int rr2=k+1; rr2<8; rr2++) {
                float f = M[rr2][k]*inv;
                for (int c=k+1;c<8;c++) M[rr2][c] -= f*M[k][c];
            }
        }
        s_dsign[tid]=sign; s_dld[tid]=ld;
    }
    __syncthreads();

    // ---- combine determinants ----
    if (tid==0) {
        float mmax=-INFINITY;
        float ldt[NDET], sg[NDET];
        #pragma unroll
        for (int d=0;d<NDET;d++) {
            ldt[d]=s_dld[d]+s_dld[16+d];
            sg[d] =s_dsign[d]*s_dsign[16+d];
            mmax = fmaxf(mmax, ldt[d]);
        }
        float psi=0.f;
        #pragma unroll
        for (int d=0;d<NDET;d++) psi += sg[d]*expf(ldt[d]-mmax)*__ldg(&wfW[d]);
        out[b] = logf(fabsf(psi)) + mmax;
    }
}

extern "C" void kernel_launch(void* const* d_in, const int* in_sizes, int n_in,
                              void* d_out, int out_size) {
    const float* r   = (const float*)d_in[0];
    const float* a   = (const float*)d_in[1];
    const float* sW0 = (const float*)d_in[2];
    const float* sb0 = (const float*)d_in[3];
    const float* sW  = (const float*)d_in[4];
    const float* sb  = (const float*)d_in[5];
    const float* pW0 = (const float*)d_in[6];
    const float* pb0 = (const float*)d_in[7];
    const float* pW  = (const float*)d_in[8];
    const float* pb  = (const float*)d_in[9];
    const float* vW  = (const float*)d_in[10];
    const float* vb  = (const float*)d_in[11];
    const float* wuW = (const float*)d_in[12];
    const float* wub = (const float*)d_in[13];
    const float* wdW = (const float*)d_in[14];
    const float* wdb = (const float*)d_in[15];
    const float* wfW = (const float*)d_in[16];
    float* out = (float*)d_out;

    int B = in_sizes[0] / (NE*3);
    ansatz_kernel<<<B, 256>>>(r,a,sW0,sb0,sW,sb,pW0,pb0,pW,pb,vW,vb,
                              wuW,wub,wdW,wdb,wfW,out);
}

// round 14
// speedup vs baseline: 1.1930x; 1.0965x over previous
#include <cuda_runtime.h>
#include <math.h>

#define NE   16
#define NU   8
#define NA   4
#define NSV  256
#define NPV  32
#define NFB  4
#define NDET 16
#define SVOUT 832   // 3*NSV + 2*NPV
#define S0IN  56    // 3*(4*NA) + 2*4
#define NLAY 5      // 4 residual layers + final vW layer

__global__ __launch_bounds__(256, 3)
void ansatz_kernel(const float* __restrict__ r,   const float* __restrict__ a,
                   const float* __restrict__ sW0, const float* __restrict__ sb0,
                   const float* __restrict__ sW,  const float* __restrict__ sb,
                   const float* __restrict__ pW0, const float* __restrict__ pb0,
                   const float* __restrict__ pW,  const float* __restrict__ pb,
                   const float* __restrict__ vW,  const float* __restrict__ vb,
                   const float* __restrict__ wuW, const float* __restrict__ wub,
                   const float* __restrict__ wdW, const float* __restrict__ wdb,
                   const float* __restrict__ wfW, float* __restrict__ out)
{
    __shared__ __align__(16) float s_sv[NE][NSV];            // 16 KB
    __shared__ __align__(16) float s_blk0[NE][S0IN];         // 3.5 KB (aliased by s_gg later)
    __shared__ __align__(16) float s_mumd[2*NSV];            // 2 KB  (mu || md)
    __shared__ __align__(16) float s_puL[NLAY][NE][NPV];     // 10 KB
    __shared__ __align__(16) float s_pdL[NLAY][NE][NPV];     // 10 KB
    __shared__ __align__(16) float s_pw[NPV*NPV];            // 4 KB
    __shared__ float s_pb[NPV];
    __shared__ float s_pu0[NE][4], s_pd0[NE][4];
    __shared__ float s_r[NE][3];
    __shared__ float s_a[NA][3];
    __shared__ float s_env[NE];
    __shared__ float s_dsign[32], s_dld[32];
    // aliases over dead regions:
    float (*s_sw)[8][128] = reinterpret_cast<float(*)[8][128]>(&s_puL[0][0][0]); // after s-phase
    float* s_gg = reinterpret_cast<float*>(&s_blk0[0][0]);                       // after layer 0

    const int tid = threadIdx.x;
    const int b   = blockIdx.x;

    // ---- load geometry ----
    if (tid < NE*3) ((float*)s_r)[tid] = r[b*NE*3 + tid];
    if (tid < NA*3) ((float*)s_a)[tid] = a[tid];
    for (int i = tid; i < NLAY*NE*NPV; i += 256) {
        ((float*)s_puL)[i] = 0.f;
        ((float*)s_pdL)[i] = 0.f;
    }
    if (tid < 64) { int e=tid>>2, c=tid&3; s_pu0[e][c]=0.f; s_pd0[e][c]=0.f; }
    __syncthreads();

    // ---- ra features -> blk0 cols [0,16) ----
    if (tid < NE*NA) {
        int e = tid >> 2, at = tid & 3;
        float dx = s_r[e][0]-s_a[at][0];
        float dy = s_r[e][1]-s_a[at][1];
        float dz = s_r[e][2]-s_a[at][2];
        float len = sqrtf(dx*dx+dy*dy+dz*dz);
        s_blk0[e][at*4+0]=dx; s_blk0[e][at*4+1]=dy;
        s_blk0[e][at*4+2]=dz; s_blk0[e][at*4+3]=len;
    }
    // ---- p0 features: thread owns pair (pi, pj) ----
    const int pi = tid >> 4;
    const int pj = tid & 15;
    float p0[4];
    {
        float dx = s_r[pj][0]-s_r[pi][0];
        float dy = s_r[pj][1]-s_r[pi][1];
        float dz = s_r[pj][2]-s_r[pi][2];
        float ax=dx, ay=dy, az=dz;
        if (pi==pj) { ax+=1.f; ay+=1.f; az+=1.f; }
        p0[0]=dx; p0[1]=dy; p0[2]=dz; p0[3]=sqrtf(ax*ax+ay*ay+az*az);
    }
    __syncthreads();

    // ---- envelope ----
    if (tid < NE) {
        float s=0.f;
        #pragma unroll
        for (int at=0; at<NA; ++at) s += expf(-s_blk0[tid][at*4+3]);
        s_env[tid]=s;
    }
    // ---- mu0/md0 -> blk0 cols [16,48) ----
    if (tid < 16) {
        float mu=0.f, md=0.f;
        for (int e=0;e<8;e++)  mu += s_blk0[e][tid];
        for (int e=8;e<16;e++) md += s_blk0[e][tid];
        mu *= 0.125f; md *= 0.125f;
        for (int e=0;e<NE;e++){ s_blk0[e][16+tid]=mu; s_blk0[e][32+tid]=md; }
    }
    // ---- raw p means ----
    {
        float* dst = (pi<NU) ? &s_pu0[pj][0] : &s_pd0[pj][0];
        #pragma unroll
        for (int c=0;c<4;c++) atomicAdd(&dst[c], p0[c]*0.125f);
    }
    if (tid < 128) s_pw[tid] = pW0[tid];
    if (tid < NPV) s_pb[tid] = pb0[tid];
    __syncthreads();
    if (tid < 64) {
        int e=tid>>2, c=tid&3;
        s_blk0[e][48+c]=s_pu0[e][c];
        s_blk0[e][52+c]=s_pd0[e][c];
    }
    __syncthreads();

    // ---- p layer 0: pv = tanh(p0 @ pW0 + pb0) ----
    float pv[NPV];
    {
        #pragma unroll
        for (int c=0;c<NPV;c++) pv[c]=s_pb[c];
        #pragma unroll
        for (int k=0;k<4;k++) {
            float aa = p0[k];
            #pragma unroll
            for (int c=0;c<NPV;c++) pv[c] += aa*s_pw[k*NPV+c];
        }
        #pragma unroll
        for (int c=0;c<NPV;c++) pv[c]=tanhf(pv[c]);
    }

    // ---- s layer 0: s_v = tanh(blk0 @ sW0 + sb0) (small; scalar form) ----
    {
        const int j = tid;
        float a0[NE];
        float bb = __ldg(&sb0[j]);
        #pragma unroll
        for (int e=0;e<NE;e++) a0[e]=bb;
        for (int k=0;k<S0IN;k++) {
            float w = __ldg(&sW0[k*NSV+j]);
            #pragma unroll
            for (int e=0;e<NE;e++) a0[e] += s_blk0[e][k]*w;
        }
        #pragma unroll
        for (int e=0;e<NE;e++) s_sv[e][tid]=tanhf(a0[e]);
    }

    // ================= p-stream phase: all p layers, snapshot means =================
    for (int i=0; i<NLAY; ++i) {
        {
            float* dst = (pi<NU)? &s_puL[i][pj][0] : &s_pdL[i][pj][0];
            #pragma unroll
            for (int c=0;c<NPV;c++) atomicAdd(&dst[c], pv[c]*0.125f);
        }
        if (i<NFB) {
            __syncthreads();
            #pragma unroll
            for (int q=0;q<4;q++) s_pw[tid+q*256] = pW[i*NPV*NPV + tid + q*256];
            if (tid<NPV) s_pb[tid]=pb[i*NPV+tid];
            __syncthreads();
            float pn[NPV];
            #pragma unroll
            for (int c=0;c<NPV;c++) pn[c]=s_pb[c];
            #pragma unroll
            for (int k=0;k<NPV;k++) {
                float aa=pv[k];
                #pragma unroll
                for (int c=0;c<NPV;c+=4) {
                    float4 w4 = *(const float4*)&s_pw[k*NPV+c];
                    pn[c]+=aa*w4.x; pn[c+1]+=aa*w4.y; pn[c+2]+=aa*w4.z; pn[c+3]+=aa*w4.w;
                }
            }
            #pragma unroll
            for (int c=0;c<NPV;c++) pv[c]=tanhf(pn[c])+pv[c];
        }
    }
    __syncthreads();   // snapshots + s_sv + s_blk0 consumers done (s_gg may alias now)

    // ================= s-stream phase: 4x4 tiling, float4 weight loads =================
    const int jg = tid & 63;       // 4 output cols: 4*jg .. 4*jg+3
    const int eg = tid >> 6;       // 4 electrons:  4*eg .. 4*eg+3
    const int j4 = jg * 4;
    const int e4 = eg * 4;

    for (int l=0; l<NLAY; ++l) {
        // mu/md (one column per thread) + gg init with bias
        {
            float mu=0.f, md=0.f;
            #pragma unroll
            for (int e=0;e<8;e++)  mu += s_sv[e][tid];
            #pragma unroll
            for (int e=8;e<16;e++) md += s_sv[e][tid];
            s_mumd[tid]=mu*0.125f; s_mumd[NSV+tid]=md*0.125f;
        }
        const float* W    = (l<NFB)? (sW + (size_t)l*SVOUT*NSV) : vW;
        const float* bias = (l<NFB)? (sb + l*NSV) : vb;
        s_gg[tid] = __ldg(&bias[tid]);
        __syncthreads();

        // ---- mu/md contribution, distributed over e-groups (128 rows each) ----
        {
            float gx=0.f, gy=0.f, gz=0.f, gw=0.f;
            const float* Wm = W + (size_t)NSV*NSV + (size_t)(eg*128)*NSV + j4;
            for (int k=0;k<128;k+=4) {
                float4 w0 = *(const float4*)&Wm[(k+0)*NSV];
                float4 w1 = *(const float4*)&Wm[(k+1)*NSV];
                float4 w2 = *(const float4*)&Wm[(k+2)*NSV];
                float4 w3 = *(const float4*)&Wm[(k+3)*NSV];
                float4 m4 = *(const float4*)&s_mumd[eg*128 + k];
                gx = fmaf(m4.x,w0.x,fmaf(m4.y,w1.x,fmaf(m4.z,w2.x,fmaf(m4.w,w3.x,gx))));
                gy = fmaf(m4.x,w0.y,fmaf(m4.y,w1.y,fmaf(m4.z,w2.y,fmaf(m4.w,w3.y,gy))));
                gz = fmaf(m4.x,w0.z,fmaf(m4.y,w1.z,fmaf(m4.z,w2.z,fmaf(m4.w,w3.z,gz))));
                gw = fmaf(m4.x,w0.w,fmaf(m4.y,w1.w,fmaf(m4.z,w2.w,fmaf(m4.w,w3.w,gw))));
            }
            atomicAdd(&s_gg[j4+0], gx);
            atomicAdd(&s_gg[j4+1], gy);
            atomicAdd(&s_gg[j4+2], gz);
            atomicAdd(&s_gg[j4+3], gw);
        }

        // ---- per-electron accumulators: s_v + pu/pd contributions ----
        float acc[4][4];
        #pragma unroll
        for (int e=0;e<4;e++) { acc[e][0]=0.f; acc[e][1]=0.f; acc[e][2]=0.f; acc[e][3]=0.f; }

        // s_v contribution
        for (int k=0;k<NSV;k+=4) {
            float4 w0 = *(const float4*)&W[(size_t)(k+0)*NSV + j4];
            float4 w1 = *(const float4*)&W[(size_t)(k+1)*NSV + j4];
            float4 w2 = *(const float4*)&W[(size_t)(k+2)*NSV + j4];
            float4 w3 = *(const float4*)&W[(size_t)(k+3)*NSV + j4];
            #pragma unroll
            for (int e=0;e<4;e++) {
                float4 s4 = *(const float4*)&s_sv[e4+e][k];
                acc[e][0] = fmaf(s4.x,w0.x,fmaf(s4.y,w1.x,fmaf(s4.z,w2.x,fmaf(s4.w,w3.x,acc[e][0]))));
                acc[e][1] = fmaf(s4.x,w0.y,fmaf(s4.y,w1.y,fmaf(s4.z,w2.y,fmaf(s4.w,w3.y,acc[e][1]))));
                acc[e][2] = fmaf(s4.x,w0.z,fmaf(s4.y,w1.z,fmaf(s4.z,w2.z,fmaf(s4.w,w3.z,acc[e][2]))));
                acc[e][3] = fmaf(s4.x,w0.w,fmaf(s4.y,w1.w,fmaf(s4.z,w2.w,fmaf(s4.w,w3.w,acc[e][3]))));
            }
        }
        // pu contribution (rows 3*NSV .. 3*NSV+31)
        {
            const float* Wu = W + (size_t)(3*NSV)*NSV + j4;
            for (int k=0;k<NPV;k+=4) {
                float4 w0 = *(const float4*)&Wu[(size_t)(k+0)*NSV];
                float4 w1 = *(const float4*)&Wu[(size_t)(k+1)*NSV];
                float4 w2 = *(const float4*)&Wu[(size_t)(k+2)*NSV];
                float4 w3 = *(const float4*)&Wu[(size_t)(k+3)*NSV];
                #pragma unroll
                for (int e=0;e<4;e++) {
                    float4 u4 = *(const float4*)&s_puL[l][e4+e][k];
                    acc[e][0] = fmaf(u4.x,w0.x,fmaf(u4.y,w1.x,fmaf(u4.z,w2.x,fmaf(u4.w,w3.x,acc[e][0]))));
                    acc[e][1] = fmaf(u4.x,w0.y,fmaf(u4.y,w1.y,fmaf(u4.z,w2.y,fmaf(u4.w,w3.y,acc[e][1]))));
                    acc[e][2] = fmaf(u4.x,w0.z,fmaf(u4.y,w1.z,fmaf(u4.z,w2.z,fmaf(u4.w,w3.z,acc[e][2]))));
                    acc[e][3] = fmaf(u4.x,w0.w,fmaf(u4.y,w1.w,fmaf(u4.z,w2.w,fmaf(u4.w,w3.w,acc[e][3]))));
                }
            }
        }
        // pd contribution (rows 3*NSV+32 .. 3*NSV+63)
        {
            const float* Wd = W + (size_t)(3*NSV+NPV)*NSV + j4;
            for (int k=0;k<NPV;k+=4) {
                float4 w0 = *(const float4*)&Wd[(size_t)(k+0)*NSV];
                float4 w1 = *(const float4*)&Wd[(size_t)(k+1)*NSV];
                float4 w2 = *(const float4*)&Wd[(size_t)(k+2)*NSV];
                float4 w3 = *(const float4*)&Wd[(size_t)(k+3)*NSV];
                #pragma unroll
                for (int e=0;e<4;e++) {
                    float4 d4 = *(const float4*)&s_pdL[l][e4+e][k];
                    acc[e][0] = fmaf(d4.x,w0.x,fmaf(d4.y,w1.x,fmaf(d4.z,w2.x,fmaf(d4.w,w3.x,acc[e][0]))));
                    acc[e][1] = fmaf(d4.x,w0.y,fmaf(d4.y,w1.y,fmaf(d4.z,w2.y,fmaf(d4.w,w3.y,acc[e][1]))));
                    acc[e][2] = fmaf(d4.x,w0.z,fmaf(d4.y,w1.z,fmaf(d4.z,w2.z,fmaf(d4.w,w3.z,acc[e][2]))));
                    acc[e][3] = fmaf(d4.x,w0.w,fmaf(d4.y,w1.w,fmaf(d4.z,w2.w,fmaf(d4.w,w3.w,acc[e][3]))));
                }
            }
        }

        // residual reads (exclusive owner of (e,j4..j4+3))
        float4 old4[4];
        if (l<NFB) {
            #pragma unroll
            for (int e=0;e<4;e++) old4[e] = *(const float4*)&s_sv[e4+e][j4];
        }
        __syncthreads();   // gg atomics done; all GEMM reads of s_sv complete

        float4 g = *(const float4*)&s_gg[j4];
        #pragma unroll
        for (int e=0;e<4;e++) {
            float t0 = tanhf(acc[e][0]+g.x);
            float t1 = tanhf(acc[e][1]+g.y);
            float t2 = tanhf(acc[e][2]+g.z);
            float t3 = tanhf(acc[e][3]+g.w);
            float4 nv;
            if (l<NFB) { nv.x=t0+old4[e].x; nv.y=t1+old4[e].y; nv.z=t2+old4[e].z; nv.w=t3+old4[e].w; }
            else       { nv.x=t0; nv.y=t1; nv.z=t2; nv.w=t3; }
            *(float4*)&s_sv[e4+e][j4] = nv;
        }
        __syncthreads();   // new s_sv visible
    }
    // snapshots 0..3 now dead -> s_sw may alias

    // ---- orbitals: thread = (spin, eg2 of 2 e, jg of 4 cols) ----
    {
        const int spin = tid >> 7;
        const int t7   = tid & 127;
        const int ojg  = t7 >> 2;        // 0..31 -> cols 4*ojg
        const int oeg  = t7 & 3;         // 0..3  -> electrons 2*oeg, 2*oeg+1
        const int oj4  = ojg * 4;
        const float* Wo = spin? wdW : wuW;
        const float* bo = spin? wdb : wub;
        float4 b4 = *(const float4*)&bo[oj4];
        float oa[2][4];
        #pragma unroll
        for (int i=0;i<2;i++) { oa[i][0]=b4.x; oa[i][1]=b4.y; oa[i][2]=b4.z; oa[i][3]=b4.w; }
        const int ebase = spin*8 + oeg*2;
        for (int k=0;k<NSV;k+=4) {
            float4 w0 = *(const float4*)&Wo[(size_t)(k+0)*128 + oj4];
            float4 w1 = *(const float4*)&Wo[(size_t)(k+1)*128 + oj4];
            float4 w2 = *(const float4*)&Wo[(size_t)(k+2)*128 + oj4];
            float4 w3 = *(const float4*)&Wo[(size_t)(k+3)*128 + oj4];
            #pragma unroll
            for (int i=0;i<2;i++) {
                float4 s4 = *(const float4*)&s_sv[ebase+i][k];
                oa[i][0] = fmaf(s4.x,w0.x,fmaf(s4.y,w1.x,fmaf(s4.z,w2.x,fmaf(s4.w,w3.x,oa[i][0]))));
                oa[i][1] = fmaf(s4.x,w0.y,fmaf(s4.y,w1.y,fmaf(s4.z,w2.y,fmaf(s4.w,w3.y,oa[i][1]))));
                oa[i][2] = fmaf(s4.x,w0.z,fmaf(s4.y,w1.z,fmaf(s4.z,w2.z,fmaf(s4.w,w3.z,oa[i][2]))));
                oa[i][3] = fmaf(s4.x,w0.w,fmaf(s4.y,w1.w,fmaf(s4.z,w2.w,fmaf(s4.w,w3.w,oa[i][3]))));
            }
        }
        __syncthreads();   // s_sv reads done before s_sw (aliases s_puL) is written
        #pragma unroll
        for (int i=0;i<2;i++) {
            float4 v; v.x=oa[i][0]; v.y=oa[i][1]; v.z=oa[i][2]; v.w=oa[i][3];
            *(float4*)&s_sw[spin][oeg*2+i][oj4] = v;
        }
    }
    __syncthreads();

    // ---- 32 slogdets of 8x8 (one per thread) ----
    if (tid < 32) {
        const int spin = tid>>4, d = tid&15;
        float M[8][8];
        for (int jr=0;jr<8;jr++)
            for (int ic=0;ic<8;ic++)
                M[jr][ic] = s_sw[spin][ic][jr*NDET+d] * s_env[spin*8+ic];
        float sign=1.f, ld=0.f;
        for (int k=0;k<8;k++) {
            int p=k; float mv=fabsf(M[k][k]);
            for (int rr2=k+1; rr2<8; rr2++) { float v=fabsf(M[rr2][k]); if (v>mv){mv=v;p=rr2;} }
            if (p!=k) { for (int c=0;c<8;c++){float t=M[k][c];M[k][c]=M[p][c];M[p][c]=t;} sign=-sign; }
            float piv = M[k][k];
            if (piv<0.f) sign=-sign;
            ld += logf(fabsf(piv));
            float inv = 1.f/piv;
            for (int rr2=k+1; rr2<8; rr2++) {
                float f = M[rr2][k]*inv;
                for (int c=k+1;c<8;c++) M[rr2][c] -= f*M[k][c];
            }
        }
        s_dsign[tid]=sign; s_dld[tid]=ld;
    }
    __syncthreads();

    // ---- combine determinants ----
    if (tid==0) {
        float mmax=-INFINITY;
        float ldt[NDET], sg[NDET];
        #pragma unroll
        for (int d=0;d<NDET;d++) {
            ldt[d]=s_dld[d]+s_dld[16+d];
            sg[d] =s_dsign[d]*s_dsign[16+d];
            mmax = fmaxf(mmax, ldt[d]);
        }
        float psi=0.f;
        #pragma unroll
        for (int d=0;d<NDET;d++) psi += sg[d]*expf(ldt[d]-mmax)*__ldg(&wfW[d]);
        out[b] = logf(fabsf(psi)) + mmax;
    }
}

extern "C" void kernel_launch(void* const* d_in, const int* in_sizes, int n_in,
                              void* d_out, int out_size) {
    const float* r   = (const float*)d_in[0];
    const float* a   = (const float*)d_in[1];
    const float* sW0 = (const float*)d_in[2];
    const float* sb0 = (const float*)d_in[3];
    const float* sW  = (const float*)d_in[4];
    const float* sb  = (const float*)d_in[5];
    const float* pW0 = (const float*)d_in[6];
    const float* pb0 = (const float*)d_in[7];
    const float* pW  = (const float*)d_in[8];
    const float* pb  = (const float*)d_in[9];
    const float* vW  = (const float*)d_in[10];
    const float* vb  = (const float*)d_in[11];
    const float* wuW = (const float*)d_in[12];
    const float* wub = (const float*)d_in[13];
    const float* wdW = (const float*)d_in[14];
    const float* wdb = (const float*)d_in[15];
    const float* wfW = (const float*)d_in[16];
    float* out = (float*)d_out;

    int B = in_sizes[0] / (NE*3);
    ansatz_kernel<<<B, 256>>>(r,a,sW0,sb0,sW,sb,pW0,pb0,pW,pb,vW,vb,
                              wuW,wub,wdW,wdb,wfW,out);
}

// round 15
// speedup vs baseline: 1.2820x; 1.0746x over previous
#include <cuda_runtime.h>
#include <math.h>

#define NE   16
#define NU   8
#define NA   4
#define NSV  256
#define NPV  32
#define NFB  4
#define NDET 16
#define SVOUT 832   // 3*NSV + 2*NPV
#define S0IN  56    // 3*(4*NA) + 2*4
#define NLAY 5      // 4 residual layers + final vW layer

// packed f32x2 helpers (sm_103a)
#define FFMA2(acc, s2, w2) \
    asm("fma.rn.f32x2 %0, %1, %2, %0;" : "+l"(acc) : "l"(s2), "l"(w2))
#define SPLAT(d, f) \
    asm("mov.b64 %0, {%1, %1};" : "=l"(d) : "r"(__float_as_uint(f)))

struct __align__(16) SmemLayout {
    float part[4][NE][NSV];     // 64 KB  split-k partials (aliased by s_sw later)
    float sv[NE][NSV];          // 16 KB
    float puL[NLAY][NE][NPV];   // 10 KB  p-mean snapshots (up)
    float pdL[NLAY][NE][NPV];   // 10 KB  (down)
    float mumd[2*NSV];          // 2 KB   mu || md
    float pw[NPV*NPV];          // 4 KB
    float gg[NSV];              // 1 KB   bias + mu/md contribution
    float blk0[NE][S0IN];       // 3.5 KB
    float pb[NPV];
    float pu0[NE][4];
    float pd0[NE][4];
    float rr[NE][3];
    float aa[NA][3];
    float env[NE];
    float dsign[32];
    float dld[32];
};

__global__ __launch_bounds__(256, 2)
void ansatz_kernel(const float* __restrict__ r,   const float* __restrict__ a,
                   const float* __restrict__ sW0, const float* __restrict__ sb0,
                   const float* __restrict__ sW,  const float* __restrict__ sb,
                   const float* __restrict__ pW0, const float* __restrict__ pb0,
                   const float* __restrict__ pW,  const float* __restrict__ pb,
                   const float* __restrict__ vW,  const float* __restrict__ vb,
                   const float* __restrict__ wuW, const float* __restrict__ wub,
                   const float* __restrict__ wdW, const float* __restrict__ wdb,
                   const float* __restrict__ wfW, float* __restrict__ out)
{
    extern __shared__ __align__(16) char smem_raw[];
    SmemLayout* S = reinterpret_cast<SmemLayout*>(smem_raw);
    // orbital buffer aliases the (then-dead) partial buffer
    float (*s_sw)[8][128] = reinterpret_cast<float(*)[8][128]>(&S->part[0][0][0]);

    const int tid = threadIdx.x;
    const int b   = blockIdx.x;

    // ---- load geometry ----
    if (tid < NE*3) ((float*)S->rr)[tid] = r[b*NE*3 + tid];
    if (tid < NA*3) ((float*)S->aa)[tid] = a[tid];
    for (int i = tid; i < NLAY*NE*NPV; i += 256) {
        ((float*)S->puL)[i] = 0.f;
        ((float*)S->pdL)[i] = 0.f;
    }
    if (tid < 64) { int e=tid>>2, c=tid&3; S->pu0[e][c]=0.f; S->pd0[e][c]=0.f; }
    __syncthreads();

    // ---- ra features -> blk0 cols [0,16) ----
    if (tid < NE*NA) {
        int e = tid >> 2, at = tid & 3;
        float dx = S->rr[e][0]-S->aa[at][0];
        float dy = S->rr[e][1]-S->aa[at][1];
        float dz = S->rr[e][2]-S->aa[at][2];
        float len = sqrtf(dx*dx+dy*dy+dz*dz);
        S->blk0[e][at*4+0]=dx; S->blk0[e][at*4+1]=dy;
        S->blk0[e][at*4+2]=dz; S->blk0[e][at*4+3]=len;
    }
    // ---- p0 features: thread owns pair (pi, pj) ----
    const int pi = tid >> 4;
    const int pj = tid & 15;
    float p0[4];
    {
        float dx = S->rr[pj][0]-S->rr[pi][0];
        float dy = S->rr[pj][1]-S->rr[pi][1];
        float dz = S->rr[pj][2]-S->rr[pi][2];
        float ax=dx, ay=dy, az=dz;
        if (pi==pj) { ax+=1.f; ay+=1.f; az+=1.f; }
        p0[0]=dx; p0[1]=dy; p0[2]=dz; p0[3]=sqrtf(ax*ax+ay*ay+az*az);
    }
    __syncthreads();

    // ---- envelope ----
    if (tid < NE) {
        float s=0.f;
        #pragma unroll
        for (int at=0; at<NA; ++at) s += expf(-S->blk0[tid][at*4+3]);
        S->env[tid]=s;
    }
    // ---- mu0/md0 -> blk0 cols [16,48) ----
    if (tid < 16) {
        float mu=0.f, md=0.f;
        for (int e=0;e<8;e++)  mu += S->blk0[e][tid];
        for (int e=8;e<16;e++) md += S->blk0[e][tid];
        mu *= 0.125f; md *= 0.125f;
        for (int e=0;e<NE;e++){ S->blk0[e][16+tid]=mu; S->blk0[e][32+tid]=md; }
    }
    // ---- raw p means ----
    {
        float* dst = (pi<NU) ? &S->pu0[pj][0] : &S->pd0[pj][0];
        #pragma unroll
        for (int c=0;c<4;c++) atomicAdd(&dst[c], p0[c]*0.125f);
    }
    if (tid < 128) S->pw[tid] = pW0[tid];
    if (tid < NPV) S->pb[tid] = pb0[tid];
    __syncthreads();
    if (tid < 64) {
        int e=tid>>2, c=tid&3;
        S->blk0[e][48+c]=S->pu0[e][c];
        S->blk0[e][52+c]=S->pd0[e][c];
    }
    __syncthreads();

    // ---- p layer 0: pv = tanh(p0 @ pW0 + pb0) ----
    float pv[NPV];
    {
        #pragma unroll
        for (int c=0;c<NPV;c++) pv[c]=S->pb[c];
        #pragma unroll
        for (int k=0;k<4;k++) {
            float aa = p0[k];
            #pragma unroll
            for (int c=0;c<NPV;c++) pv[c] += aa*S->pw[k*NPV+c];
        }
        #pragma unroll
        for (int c=0;c<NPV;c++) pv[c]=tanhf(pv[c]);
    }

    // ---- s layer 0: s_v = tanh(blk0 @ sW0 + sb0) (small; scalar form) ----
    {
        const int j = tid;
        float a0[NE];
        float bb = sb0[j];
        #pragma unroll
        for (int e=0;e<NE;e++) a0[e]=bb;
        for (int k=0;k<S0IN;k++) {
            float w = sW0[k*NSV+j];
            #pragma unroll
            for (int e=0;e<NE;e++) a0[e] += S->blk0[e][k]*w;
        }
        #pragma unroll
        for (int e=0;e<NE;e++) S->sv[e][tid]=tanhf(a0[e]);
    }

    // ================= p-stream phase: all p layers, snapshot means =================
    for (int i=0; i<NLAY; ++i) {
        {
            float* dst = (pi<NU)? &S->puL[i][pj][0] : &S->pdL[i][pj][0];
            #pragma unroll
            for (int c=0;c<NPV;c++) atomicAdd(&dst[c], pv[c]*0.125f);
        }
        if (i<NFB) {
            __syncthreads();
            #pragma unroll
            for (int q=0;q<4;q++) S->pw[tid+q*256] = pW[i*NPV*NPV + tid + q*256];
            if (tid<NPV) S->pb[tid]=pb[i*NPV+tid];
            __syncthreads();
            float pn[NPV];
            #pragma unroll
            for (int c=0;c<NPV;c++) pn[c]=S->pb[c];
            #pragma unroll
            for (int k=0;k<NPV;k++) {
                float aa=pv[k];
                #pragma unroll
                for (int c=0;c<NPV;c+=4) {
                    float4 w4 = *(const float4*)&S->pw[k*NPV+c];
                    pn[c]+=aa*w4.x; pn[c+1]+=aa*w4.y; pn[c+2]+=aa*w4.z; pn[c+3]+=aa*w4.w;
                }
            }
            #pragma unroll
            for (int c=0;c<NPV;c++) pv[c]=tanhf(pn[c])+pv[c];
        }
    }
    __syncthreads();   // snapshots + sv visible

    // ================= s-stream phase: split-k (4 way) × 4-col tiles, f32x2 =================
    const int kg = tid >> 6;       // k-quarter owner
    const int jg = tid & 63;       // 4 output cols: j4..j4+3
    const int j4 = jg * 4;

    for (int l=0; l<NLAY; ++l) {
        // mu/md vectors (one column per thread) + gg init with bias
        {
            float mu=0.f, md=0.f;
            #pragma unroll
            for (int e=0;e<8;e++)  mu += S->sv[e][tid];
            #pragma unroll
            for (int e=8;e<16;e++) md += S->sv[e][tid];
            S->mumd[tid]=mu*0.125f; S->mumd[NSV+tid]=md*0.125f;
        }
        const float* W    = (l<NFB)? (sW + (size_t)l*SVOUT*NSV) : vW;
        const float* bias = (l<NFB)? (sb + l*NSV) : vb;
        S->gg[tid] = bias[tid];
        __syncthreads();

        // ---- mu/md contribution: kg owns 128 of the 512 rows ----
        {
            float gx=0.f, gy=0.f, gz=0.f, gw=0.f;
            const float* Wm = W + (size_t)NSV*NSV + (size_t)(kg*128)*NSV + j4;
            for (int k=0;k<128;k+=4) {
                float4 w0 = *(const float4*)&Wm[(size_t)(k+0)*NSV];
                float4 w1 = *(const float4*)&Wm[(size_t)(k+1)*NSV];
                float4 w2 = *(const float4*)&Wm[(size_t)(k+2)*NSV];
                float4 w3 = *(const float4*)&Wm[(size_t)(k+3)*NSV];
                float4 m4 = *(const float4*)&S->mumd[kg*128 + k];
                gx = fmaf(m4.x,w0.x,fmaf(m4.y,w1.x,fmaf(m4.z,w2.x,fmaf(m4.w,w3.x,gx))));
                gy = fmaf(m4.x,w0.y,fmaf(m4.y,w1.y,fmaf(m4.z,w2.y,fmaf(m4.w,w3.y,gy))));
                gz = fmaf(m4.x,w0.z,fmaf(m4.y,w1.z,fmaf(m4.z,w2.z,fmaf(m4.w,w3.z,gz))));
                gw = fmaf(m4.x,w0.w,fmaf(m4.y,w1.w,fmaf(m4.z,w2.w,fmaf(m4.w,w3.w,gw))));
            }
            atomicAdd(&S->gg[j4+0], gx);
            atomicAdd(&S->gg[j4+1], gy);
            atomicAdd(&S->gg[j4+2], gz);
            atomicAdd(&S->gg[j4+3], gw);
        }

        // ---- packed partial accumulators: all 16 electrons, 4 cols (2 f32x2 pairs) ----
        unsigned long long acc0[NE], acc1[NE];
        #pragma unroll
        for (int e=0;e<NE;e++) { acc0[e]=0ull; acc1[e]=0ull; }

        // s_v partial over k in [kg*64, kg*64+64)
        {
            const float* Wr0 = W + (size_t)(kg*64)*NSV + j4;
            const float* sv0 = &S->sv[0][kg*64];
            #pragma unroll 1
            for (int kk=0; kk<64; kk+=4) {
                const float* Wr = Wr0 + (size_t)kk*NSV;
                ulonglong2 w0 = *(const ulonglong2*)(Wr);
                ulonglong2 w1 = *(const ulonglong2*)(Wr +   NSV);
                ulonglong2 w2 = *(const ulonglong2*)(Wr + 2*NSV);
                ulonglong2 w3 = *(const ulonglong2*)(Wr + 3*NSV);
                #pragma unroll
                for (int e=0;e<NE;e++) {
                    float4 s4 = *(const float4*)(sv0 + e*NSV + kk);
                    unsigned long long t;
                    SPLAT(t, s4.x); FFMA2(acc0[e], t, w0.x); FFMA2(acc1[e], t, w0.y);
                    SPLAT(t, s4.y); FFMA2(acc0[e], t, w1.x); FFMA2(acc1[e], t, w1.y);
                    SPLAT(t, s4.z); FFMA2(acc0[e], t, w2.x); FFMA2(acc1[e], t, w2.y);
                    SPLAT(t, s4.w); FFMA2(acc0[e], t, w3.x); FFMA2(acc1[e], t, w3.y);
                }
            }
        }
        // pu/pd partial: kg owns 16 of the 64 rows (kg 0,1 -> pu; kg 2,3 -> pd)
        {
            const float* act = (kg<2)? &S->puL[l][0][0] : &S->pdL[l][0][0];
            const int   r0  = (kg&1)*16;
            const float* Wp0 = W + (size_t)(3*NSV + kg*16)*NSV + j4;
            #pragma unroll 1
            for (int kk=0; kk<16; kk+=4) {
                const float* Wr = Wp0 + (size_t)kk*NSV;
                ulonglong2 w0 = *(const ulonglong2*)(Wr);
                ulonglong2 w1 = *(const ulonglong2*)(Wr +   NSV);
                ulonglong2 w2 = *(const ulonglong2*)(Wr + 2*NSV);
                ulonglong2 w3 = *(const ulonglong2*)(Wr + 3*NSV);
                #pragma unroll
                for (int e=0;e<NE;e++) {
                    float4 s4 = *(const float4*)&act[e*NPV + r0 + kk];
                    unsigned long long t;
                    SPLAT(t, s4.x); FFMA2(acc0[e], t, w0.x); FFMA2(acc1[e], t, w0.y);
                    SPLAT(t, s4.y); FFMA2(acc0[e], t, w1.x); FFMA2(acc1[e], t, w1.y);
                    SPLAT(t, s4.z); FFMA2(acc0[e], t, w2.x); FFMA2(acc1[e], t, w2.y);
                    SPLAT(t, s4.w); FFMA2(acc0[e], t, w3.x); FFMA2(acc1[e], t, w3.y);
                }
            }
        }
        // store partials
        #pragma unroll
        for (int e=0;e<NE;e++) {
            ulonglong2 v; v.x = acc0[e]; v.y = acc1[e];
            *(ulonglong2*)&S->part[kg][e][j4] = v;
        }
        __syncthreads();   // partials + gg atomics visible; all sv reads done

        // ---- final pass: thread owns (e = tid>>4, 16 cols) ----
        {
            const int fe = tid >> 4;
            const int fj = (tid & 15) * 16;
            #pragma unroll
            for (int c=0;c<16;c+=4) {
                float4 q0 = *(const float4*)&S->part[0][fe][fj+c];
                float4 q1 = *(const float4*)&S->part[1][fe][fj+c];
                float4 q2 = *(const float4*)&S->part[2][fe][fj+c];
                float4 q3 = *(const float4*)&S->part[3][fe][fj+c];
                float4 g  = *(const float4*)&S->gg[fj+c];
                float4 nv;
                nv.x = tanhf(q0.x+q1.x+q2.x+q3.x+g.x);
                nv.y = tanhf(q0.y+q1.y+q2.y+q3.y+g.y);
                nv.z = tanhf(q0.z+q1.z+q2.z+q3.z+g.z);
                nv.w = tanhf(q0.w+q1.w+q2.w+q3.w+g.w);
                if (l<NFB) {
                    float4 old = *(const float4*)&S->sv[fe][fj+c];
                    nv.x+=old.x; nv.y+=old.y; nv.z+=old.z; nv.w+=old.w;
                }
                *(float4*)&S->sv[fe][fj+c] = nv;
            }
        }
        __syncthreads();   // new sv visible for next layer
    }
    // part is now scratch -> s_sw alias is safe

    // ---- orbitals: thread = (spin, 2 e, 4 cols) ----
    {
        const int spin = tid >> 7;
        const int t7   = tid & 127;
        const int ojg  = t7 >> 2;        // 0..31 -> cols 4*ojg
        const int oeg  = t7 & 3;         // 0..3  -> electrons 2*oeg, 2*oeg+1
        const int oj4  = ojg * 4;
        const float* Wo = spin? wdW : wuW;
        const float* bo = spin? wdb : wub;
        float4 b4 = *(const float4*)&bo[oj4];
        float oa[2][4];
        #pragma unroll
        for (int i=0;i<2;i++) { oa[i][0]=b4.x; oa[i][1]=b4.y; oa[i][2]=b4.z; oa[i][3]=b4.w; }
        const int ebase = spin*8 + oeg*2;
        for (int k=0;k<NSV;k+=4) {
            float4 w0 = *(const float4*)&Wo[(size_t)(k+0)*128 + oj4];
            float4 w1 = *(const float4*)&Wo[(size_t)(k+1)*128 + oj4];
            float4 w2 = *(const float4*)&Wo[(size_t)(k+2)*128 + oj4];
            float4 w3 = *(const float4*)&Wo[(size_t)(k+3)*128 + oj4];
            #pragma unroll
            for (int i=0;i<2;i++) {
                float4 s4 = *(const float4*)&S->sv[ebase+i][k];
                oa[i][0] = fmaf(s4.x,w0.x,fmaf(s4.y,w1.x,fmaf(s4.z,w2.x,fmaf(s4.w,w3.x,oa[i][0]))));
                oa[i][1] = fmaf(s4.x,w0.y,fmaf(s4.y,w1.y,fmaf(s4.z,w2.y,fmaf(s4.w,w3.y,oa[i][1]))));
                oa[i][2] = fmaf(s4.x,w0.z,fmaf(s4.y,w1.z,fmaf(s4.z,w2.z,fmaf(s4.w,w3.z,oa[i][2]))));
                oa[i][3] = fmaf(s4.x,w0.w,fmaf(s4.y,w1.w,fmaf(s4.z,w2.w,fmaf(s4.w,w3.w,oa[i][3]))));
            }
        }
        __syncthreads();   // sv reads done before s_sw (aliases part) is written
        #pragma unroll
        for (int i=0;i<2;i++) {
            float4 v; v.x=oa[i][0]; v.y=oa[i][1]; v.z=oa[i][2]; v.w=oa[i][3];
            *(float4*)&s_sw[spin][oeg*2+i][oj4] = v;
        }
    }
    __syncthreads();

    // ---- 32 slogdets of 8x8 (one per thread) ----
    if (tid < 32) {
        const int spin = tid>>4, d = tid&15;
        float M[8][8];
        for (int jr=0;jr<8;jr++)
            for (int ic=0;ic<8;ic++)
                M[jr][ic] = s_sw[spin][ic][jr*NDET+d] * S->env[spin*8+ic];
        float sign=1.f, ld=0.f;
        for (int k=0;k<8;k++) {
            int p=k; float mv=fabsf(M[k][k]);
            for (int rr2=k+1; rr2<8; rr2++) { float v=fabsf(M[rr2][k]); if (v>mv){mv=v;p=rr2;} }
            if (p!=k) { for (int c=0;c<8;c++){float t=M[k][c];M[k][c]=M[p][c];M[p][c]=t;} sign=-sign; }
            float piv = M[k][k];
            if (piv<0.f) sign=-sign;
            ld += logf(fabsf(piv));
            float inv = 1.f/piv;
            for (int rr2=k+1; rr2<8; rr2++) {
                float f = M[rr2][k]*inv;
                for (int c=k+1;c<8;c++) M[rr2][c] -= f*M[k][c];
            }
        }
        S->dsign[tid]=sign; S->dld[tid]=ld;
    }
    __syncthreads();

    // ---- combine determinants ----
    if (tid==0) {
        float mmax=-INFINITY;
        float ldt[NDET], sg[NDET];
        #pragma unroll
        for (int d=0;d<NDET;d++) {
            ldt[d]=S->dld[d]+S->dld[16+d];
            sg[d] =S->dsign[d]*S->dsign[16+d];
            mmax = fmaxf(mmax, ldt[d]);
        }
        float psi=0.f;
        #pragma unroll
        for (int d=0;d<NDET;d++) psi += sg[d]*expf(ldt[d]-mmax)*wfW[d];
        out[b] = logf(fabsf(psi)) + mmax;
    }
}

extern "C" void kernel_launch(void* const* d_in, const int* in_sizes, int n_in,
                              void* d_out, int out_size) {
    const float* r   = (const float*)d_in[0];
    const float* a   = (const float*)d_in[1];
    const float* sW0 = (const float*)d_in[2];
    const float* sb0 = (const float*)d_in[3];
    const float* sW  = (const float*)d_in[4];
    const float* sb  = (const float*)d_in[5];
    const float* pW0 = (const float*)d_in[6];
    const float* pb0 = (const float*)d_in[7];
    const float* pW  = (const float*)d_in[8];
    const float* pb  = (const float*)d_in[9];
    const float* vW  = (const float*)d_in[10];
    const float* vb  = (const float*)d_in[11];
    const float* wuW = (const float*)d_in[12];
    const float* wub = (const float*)d_in[13];
    const float* wdW = (const float*)d_in[14];
    const float* wdb = (const float*)d_in[15];
    const float* wfW = (const float*)d_in[16];
    float* out = (float*)d_out;

    int B = in_sizes[0] / (NE*3);
    int smem = (int)sizeof(SmemLayout);
    cudaFuncSetAttribute(ansatz_kernel,
                         cudaFuncAttributeMaxDynamicSharedMemorySize, smem);
    ansatz_kernel<<<B, 256, smem>>>(r,a,sW0,sb0,sW,sb,pW0,pb0,pW,pb,vW,vb,
                                    wuW,wub,wdW,wdb,wfW,out);
}